// round 8
// baseline (speedup 1.0000x reference)
#include <cuda_runtime.h>
#include <cuda_bf16.h>
#include <cstdint>

// Problem constants
// x: [16,1,256,256]  W_cs: [256,1,32,32]  W_init: [1024,256,1,1]
// W_first: [64,1,3,3] W_blk: [64,64,3,3]  W_last: [1,64,3,3]  a_main,a_blk: [1]
// outputs: out [16,1,256,256] | outcsy [16,256,8,8] | out_initrec [16,1,256,256]

#define NBATCH 16
#define HW     256
#define PLANE  65536            // 256*256
#define CHANS  64

#define OUT_OFF 0
#define CSY_OFF 1048576
#define IR_OFF  1310720

#define F_PRELU 1
#define F_RES   2

// 268 MB each: ping-pong feature maps [16][64][256][256]
__device__ float g_featA[NBATCH * CHANS * PLANE];
__device__ float g_featB[NBATCH * CHANS * PLANE];

// ---------------- packed fp32 helpers (sm_103a FFMA2 path) ------------------
typedef unsigned long long u64;

__device__ __forceinline__ void fma2(u64& d, u64 a, u64 b) {
    asm("fma.rn.f32x2 %0, %1, %2, %0;" : "+l"(d) : "l"(a), "l"(b));
}
__device__ __forceinline__ u64 dup2(float v) {
    u64 r; asm("mov.b64 %0, {%1, %1};" : "=l"(r) : "f"(v)); return r;
}
__device__ __forceinline__ u64 pack2(float lo, float hi) {
    u64 r; asm("mov.b64 %0, {%1, %2};" : "=l"(r) : "f"(lo), "f"(hi)); return r;
}
__device__ __forceinline__ float2 unpk2(u64 v) {
    float2 f; asm("mov.b64 {%0, %1}, %2;" : "=f"(f.x), "=f"(f.y) : "l"(v)); return f;
}

// ---------------------------------------------------------------------------
// Kernel 1: CS sampling conv. outcsy[n][oc][by][bx] = <x 32x32 patch, W_cs[oc]>
// ---------------------------------------------------------------------------
__global__ __launch_bounds__(256) void cs_k(const float* __restrict__ x,
                                            const float* __restrict__ Wcs,
                                            float* __restrict__ csy)
{
    extern __shared__ float sm1[];
    float* xs  = sm1;          // 8192 floats
    float* wsm = sm1 + 8192;   // 16384 floats

    const int t  = threadIdx.x;
    const int n  = blockIdx.x;
    const int by = blockIdx.y;

    const float* xrow = x + (n << 16) + (by << 5) * 256;
    for (int i = t; i < 8192; i += 256) xs[i] = xrow[i];

    float acc[8];
#pragma unroll
    for (int bx = 0; bx < 8; bx++) acc[bx] = 0.f;

    const float* wthr = Wcs + t * 1024;
    for (int kc = 0; kc < 1024; kc += 64) {
        __syncthreads();
#pragma unroll 8
        for (int kk = 0; kk < 64; kk++) wsm[kk * 256 + t] = wthr[kc + kk];
        __syncthreads();
#pragma unroll 4
        for (int kk = 0; kk < 64; kk++) {
            const float w = wsm[kk * 256 + t];
            const int k = kc + kk;
            const float* xp = &xs[((k >> 5) << 8) + (k & 31)];
#pragma unroll
            for (int bx = 0; bx < 8; bx++) acc[bx] = fmaf(w, xp[bx << 5], acc[bx]);
        }
    }
    float* o = csy + (n * 256 + t) * 64 + (by << 3);
#pragma unroll
    for (int bx = 0; bx < 8; bx++) o[bx] = acc[bx];
}

// ---------------------------------------------------------------------------
// Kernel 2: 1x1 init conv (256 -> 1024 ch) + depth-to-space scatter.
// ---------------------------------------------------------------------------
__global__ __launch_bounds__(256) void init_k(const float* __restrict__ csy,
                                              const float* __restrict__ Wi,
                                              float* __restrict__ irec)
{
    extern __shared__ float cs[];    // [256 c][64 pos]
    const int t = threadIdx.x;
    const int n = blockIdx.x;
    const int oc = blockIdx.y * 256 + t;

    const float* src = csy + n * 16384;
    for (int i = t; i < 16384; i += 256) cs[i] = src[i];
    __syncthreads();

    const float* wrow = Wi + oc * 256;
    const int ii = oc & 31;
    const int jj = oc >> 5;
    float* dst = irec + (n << 16);

#pragma unroll
    for (int pb = 0; pb < 64; pb += 32) {
        float acc[32];
#pragma unroll
        for (int p = 0; p < 32; p++) acc[p] = 0.f;
#pragma unroll 2
        for (int c = 0; c < 256; c++) {
            const float w = wrow[c];
            const float4* cp = (const float4*)&cs[c * 64 + pb];
#pragma unroll
            for (int p4 = 0; p4 < 8; p4++) {
                const float4 v = cp[p4];
                acc[p4 * 4 + 0] = fmaf(w, v.x, acc[p4 * 4 + 0]);
                acc[p4 * 4 + 1] = fmaf(w, v.y, acc[p4 * 4 + 1]);
                acc[p4 * 4 + 2] = fmaf(w, v.z, acc[p4 * 4 + 2]);
                acc[p4 * 4 + 3] = fmaf(w, v.w, acc[p4 * 4 + 3]);
            }
        }
#pragma unroll
        for (int p = 0; p < 32; p++) {
            const int pos = pb + p;
            const int h = pos >> 3, wq = pos & 7;
            dst[(h * 32 + ii) * 256 + wq * 32 + jj] = acc[p];
        }
    }
}

// ---------------------------------------------------------------------------
// Kernel 3: 3x3 conv, OC=64, Cin runtime (1 or 64), pad=1 — FFMA2 version.
// Tile 64(w) x 4(h). 256 threads: strip = t&31, ocg = t>>5.
// Each thread: 8 oc x 4 px-pairs of f32x2 accumulators (8 px).
// Input tile: stride 72 (16B-aligned rows), double-buffered, 1 sync per ic.
// ---------------------------------------------------------------------------
#define TSTR 72
#define TSZ  (6 * TSTR)   // 432 floats per buffer

__global__ __launch_bounds__(256) void conv3x3_k(
    const float* __restrict__ in, const float* __restrict__ wgt,
    const float* __restrict__ res, const float* __restrict__ alpha_p,
    float* __restrict__ out, int Cin, int flags)
{
    extern __shared__ float sm3[];
    float* ws   = sm3;                 // Cin*576
    float* tile = sm3 + Cin * 576;     // 2 * 432

    const int t  = threadIdx.x;
    const int n  = blockIdx.z;
    const int y0 = blockIdx.y << 2;
    const int x0 = blockIdx.x << 6;

    const int wtot = Cin * 576;
    for (int i = t; i < wtot; i += 256) ws[i] = wgt[i];

    const int strip = t & 31;
    const int ocg   = t >> 5;
    const int sy    = strip >> 3;
    const int sxb   = (strip & 7) << 3;

    u64 acc2[8][4];
#pragma unroll
    for (int o = 0; o < 8; o++)
#pragma unroll
        for (int j = 0; j < 4; j++) acc2[o][j] = 0ull;

    const float* inN = in + (size_t)n * Cin * PLANE;
    const int Cin9 = Cin * 9;

    // tile-load coordinates (logical 6x66 region, stored at stride 72)
    const int r0i = t / 66, c0i = t - r0i * 66;
    const int gy0 = y0 - 1 + r0i, gx0 = x0 - 1 + c0i;
    const bool ok0 = ((unsigned)gy0 < 256u) && ((unsigned)gx0 < 256u);
    const int off0 = gy0 * 256 + gx0;
    const int sidx0 = r0i * TSTR + c0i;
    const int idx1 = t + 256;
    const bool has1 = idx1 < 396;
    const int r1i = idx1 / 66, c1i = idx1 - r1i * 66;
    const int gy1 = y0 - 1 + r1i, gx1 = x0 - 1 + c1i;
    const bool ok1 = has1 && ((unsigned)gy1 < 256u) && ((unsigned)gx1 < 256u);
    const int off1 = gy1 * 256 + gx1;
    const int sidx1 = r1i * TSTR + c1i;

    // preload channel 0 and store to buffer 0
    {
        float v0 = ok0 ? inN[off0] : 0.f;
        float v1 = ok1 ? inN[off1] : 0.f;
        tile[sidx0] = v0;
        if (has1) tile[sidx1] = v1;
    }
    __syncthreads();

    for (int ic = 0; ic < Cin; ic++) {
        // prefetch next channel (gmem latency hidden behind compute)
        float v0 = 0.f, v1 = 0.f;
        const bool more = (ic + 1 < Cin);
        if (more) {
            const float* nx = inN + (ic + 1) * PLANE;
            v0 = ok0 ? nx[off0] : 0.f;
            v1 = ok1 ? nx[off1] : 0.f;
        }

        const float* buf = tile + (ic & 1) * TSZ;
        const float* wic = ws + (ocg << 3) * Cin9 + ic * 9;

#pragma unroll
        for (int ky = 0; ky < 3; ky++) {
            const u64* ep = (const u64*)(buf + (sy + ky) * TSTR + sxb);
            u64 e0 = ep[0], e1 = ep[1], e2 = ep[2], e3 = ep[3], e4 = ep[4];
            // kx=1 shifted pairs
            float2 a0 = unpk2(e0), a1 = unpk2(e1), a2 = unpk2(e2),
                   a3 = unpk2(e3), a4 = unpk2(e4);
            u64 m0 = pack2(a0.y, a1.x);
            u64 m1 = pack2(a1.y, a2.x);
            u64 m2 = pack2(a2.y, a3.x);
            u64 m3 = pack2(a3.y, a4.x);
#pragma unroll
            for (int o = 0; o < 8; o++) {
                const float* wo = wic + o * Cin9 + ky * 3;
                const u64 w0 = dup2(wo[0]);
                const u64 w1 = dup2(wo[1]);
                const u64 w2 = dup2(wo[2]);
                fma2(acc2[o][0], e0, w0); fma2(acc2[o][0], m0, w1); fma2(acc2[o][0], e1, w2);
                fma2(acc2[o][1], e1, w0); fma2(acc2[o][1], m1, w1); fma2(acc2[o][1], e2, w2);
                fma2(acc2[o][2], e2, w0); fma2(acc2[o][2], m2, w1); fma2(acc2[o][2], e3, w2);
                fma2(acc2[o][3], e3, w0); fma2(acc2[o][3], m3, w1); fma2(acc2[o][3], e4, w2);
            }
        }

        // write next channel into the other buffer (read/write on distinct bufs)
        if (more) {
            float* nb = tile + ((ic + 1) & 1) * TSZ;
            nb[sidx0] = v0;
            if (has1) nb[sidx1] = v1;
        }
        __syncthreads();
    }

    const float alpha = *alpha_p;
    const int y = y0 + sy, xb = x0 + sxb;
#pragma unroll
    for (int o = 0; o < 8; o++) {
        const int oc = (ocg << 3) + o;
        const size_t gbase = (((size_t)(n * CHANS + oc)) << 16) + y * 256 + xb;
        float v[8];
#pragma unroll
        for (int j = 0; j < 4; j++) {
            float2 u = unpk2(acc2[o][j]);
            v[2 * j] = u.x; v[2 * j + 1] = u.y;
        }
        if (flags & F_RES) {
            const float4* rp = (const float4*)(res + gbase);
            const float4 r0 = rp[0], r1 = rp[1];
            v[0] += r0.x; v[1] += r0.y; v[2] += r0.z; v[3] += r0.w;
            v[4] += r1.x; v[5] += r1.y; v[6] += r1.z; v[7] += r1.w;
        }
        if (flags & F_PRELU) {
#pragma unroll
            for (int p = 0; p < 8; p++) v[p] = v[p] >= 0.f ? v[p] : alpha * v[p];
        }
        float4* op = (float4*)(out + gbase);
        op[0] = make_float4(v[0], v[1], v[2], v[3]);
        op[1] = make_float4(v[4], v[5], v[6], v[7]);
    }
}

// ---------------------------------------------------------------------------
// Kernel 4: last conv: out = conv3x3(feat + broadcast(initrec), W_last).
// ---------------------------------------------------------------------------
__global__ __launch_bounds__(256) void last_k(const float* __restrict__ fin,
                                              const float* __restrict__ irec,
                                              const float* __restrict__ Wl,
                                              float* __restrict__ out)
{
    __shared__ float ws[585];
    __shared__ float tile[2340];  // 18 rows x 130

    const int t  = threadIdx.x;
    const int n  = blockIdx.z;
    const int y0 = blockIdx.y << 4;
    const int x0 = blockIdx.x << 7;

    for (int i = t; i < 576; i += 256) ws[i] = Wl[i];
    __syncthreads();
    if (t < 9) {
        float s = 0.f;
        for (int ic = 0; ic < 64; ic++) s += ws[ic * 9 + t];
        ws[576 + t] = s;
    }

    const int sy  = t >> 4;
    const int sxb = (t & 15) << 3;

    int offv[10]; bool okv[10]; bool hasv[10]; int idxv[10];
#pragma unroll
    for (int k = 0; k < 10; k++) {
        const int idx = t + k * 256;
        idxv[k] = idx;
        hasv[k] = idx < 2340;
        const int r = idx / 130, c = idx - r * 130;
        const int gy = y0 - 1 + r, gx = x0 - 1 + c;
        okv[k] = hasv[k] && ((unsigned)gy < 256u) && ((unsigned)gx < 256u);
        offv[k] = gy * 256 + gx;
    }

    float acc[8];
#pragma unroll
    for (int p = 0; p < 8; p++) acc[p] = 0.f;

    const float* src = fin + ((size_t)(n * CHANS) << 16);
    float pf[10];
#pragma unroll
    for (int k = 0; k < 10; k++) pf[k] = okv[k] ? src[offv[k]] : 0.f;

    for (int ic = 0; ic < 65; ic++) {
        __syncthreads();
#pragma unroll
        for (int k = 0; k < 10; k++) if (hasv[k]) tile[idxv[k]] = pf[k];
        __syncthreads();
        if (ic + 1 < 65) {
            const float* nx = (ic + 1 < 64)
                ? (fin + ((size_t)(n * CHANS + ic + 1) << 16))
                : (irec + ((size_t)n << 16));
#pragma unroll
            for (int k = 0; k < 10; k++) pf[k] = okv[k] ? nx[offv[k]] : 0.f;
        }
        float w[9];
#pragma unroll
        for (int q = 0; q < 9; q++) w[q] = ws[ic * 9 + q];
#pragma unroll
        for (int ky = 0; ky < 3; ky++) {
            float rv[10];
            const float* tp = &tile[(sy + ky) * 130 + sxb];
#pragma unroll
            for (int j = 0; j < 10; j++) rv[j] = tp[j];
#pragma unroll
            for (int kx = 0; kx < 3; kx++)
#pragma unroll
                for (int p = 0; p < 8; p++)
                    acc[p] = fmaf(rv[p + kx], w[ky * 3 + kx], acc[p]);
        }
    }

    const int y = y0 + sy, xb = x0 + sxb;
    float4* op = (float4*)(out + ((size_t)n << 16) + y * 256 + xb);
    op[0] = make_float4(acc[0], acc[1], acc[2], acc[3]);
    op[1] = make_float4(acc[4], acc[5], acc[6], acc[7]);
}

// ---------------------------------------------------------------------------
extern "C" void kernel_launch(void* const* d_in, const int* in_sizes, int n_in,
                              void* d_out_, int out_size)
{
    const float* x   = (const float*)d_in[0];
    const float* Wcs = (const float*)d_in[1];
    const float* Wi  = (const float*)d_in[2];
    const float* Wf  = (const float*)d_in[3];
    const float* Wb  = (const float*)d_in[4];
    const float* Wl  = (const float*)d_in[5];
    const float* am  = (const float*)d_in[6];
    const float* ab  = (const float*)d_in[7];

    float* out  = (float*)d_out_;
    float* csy  = out + CSY_OFF;
    float* irec = out + IR_OFF;

    float* fA = nullptr; float* fB = nullptr;
    cudaGetSymbolAddress((void**)&fA, g_featA);
    cudaGetSymbolAddress((void**)&fB, g_featB);

    const size_t smem64 = (size_t)(64 * 576 + 2 * TSZ) * 4;
    const size_t smem1  = (size_t)(1 * 576 + 2 * TSZ) * 4;

    cudaFuncSetAttribute(cs_k,      cudaFuncAttributeMaxDynamicSharedMemorySize, (8192 + 16384) * 4);
    cudaFuncSetAttribute(init_k,    cudaFuncAttributeMaxDynamicSharedMemorySize, 16384 * 4);
    cudaFuncSetAttribute(conv3x3_k, cudaFuncAttributeMaxDynamicSharedMemorySize, (int)smem64);

    // 1) CS sampling -> outcsy (in d_out)
    cs_k<<<dim3(16, 8), 256, (8192 + 16384) * 4>>>(x, Wcs, csy);

    // 2) 1x1 init conv + depth-to-space -> out_initrec (in d_out)
    init_k<<<dim3(16, 4), 256, 16384 * 4>>>(csy, Wi, irec);

    // 3) first conv 1->64 + PReLU(a_main) -> featA
    conv3x3_k<<<dim3(4, 64, 16), 256, smem1>>>(irec, Wf, nullptr, am, fA, 1, F_PRELU);

    // 4) 4x residual blocks with shared weights
    for (int b = 0; b < 4; b++) {
        conv3x3_k<<<dim3(4, 64, 16), 256, smem64>>>(
            fA, Wb, nullptr, ab, fB, 64, F_PRELU);
        conv3x3_k<<<dim3(4, 64, 16), 256, smem64>>>(
            fB, Wb, fA, ab, fA, 64, F_PRELU | F_RES);
    }

    // 5) last conv (feat + broadcast initrec) 64->1 -> out
    last_k<<<dim3(2, 16, 16), 256>>>(fA, irec, Wl, out);
}

// round 15
// speedup vs baseline: 3.1528x; 3.1528x over previous
#include <cuda_runtime.h>
#include <cuda_bf16.h>
#include <cstdint>

// Problem constants
// x: [16,1,256,256]  W_cs: [256,1,32,32]  W_init: [1024,256,1,1]
// W_first: [64,1,3,3] W_blk: [64,64,3,3]  W_last: [1,64,3,3]  a_main,a_blk: [1]
// outputs: out [16,1,256,256] | outcsy [16,256,8,8] | out_initrec [16,1,256,256]

#define NBATCH 16
#define HW     256
#define PLANE  65536            // 256*256
#define CHANS  64

#define OUT_OFF 0
#define CSY_OFF 1048576
#define IR_OFF  1310720

#define F_PRELU 1
#define F_RES   2

// 268 MB each: ping-pong feature maps [16][64][256][256]
__device__ float g_featA[NBATCH * CHANS * PLANE];
__device__ float g_featB[NBATCH * CHANS * PLANE];

// ---------------------------------------------------------------------------
// Kernel 1: CS sampling conv. outcsy[n][oc][by][bx] = <x 32x32 patch, W_cs[oc]>
// ---------------------------------------------------------------------------
__global__ __launch_bounds__(256) void cs_k(const float* __restrict__ x,
                                            const float* __restrict__ Wcs,
                                            float* __restrict__ csy)
{
    extern __shared__ float sm1[];
    float* xs  = sm1;          // 8192 floats
    float* wsm = sm1 + 8192;   // 16384 floats

    const int t  = threadIdx.x;
    const int n  = blockIdx.x;
    const int by = blockIdx.y;

    const float* xrow = x + (n << 16) + (by << 5) * 256;
    for (int i = t; i < 8192; i += 256) xs[i] = xrow[i];

    float acc[8];
#pragma unroll
    for (int bx = 0; bx < 8; bx++) acc[bx] = 0.f;

    const float* wthr = Wcs + t * 1024;
    for (int kc = 0; kc < 1024; kc += 64) {
        __syncthreads();
#pragma unroll 8
        for (int kk = 0; kk < 64; kk++) wsm[kk * 256 + t] = wthr[kc + kk];
        __syncthreads();
#pragma unroll 4
        for (int kk = 0; kk < 64; kk++) {
            const float w = wsm[kk * 256 + t];
            const int k = kc + kk;
            const float* xp = &xs[((k >> 5) << 8) + (k & 31)];
#pragma unroll
            for (int bx = 0; bx < 8; bx++) acc[bx] = fmaf(w, xp[bx << 5], acc[bx]);
        }
    }
    float* o = csy + (n * 256 + t) * 64 + (by << 3);
#pragma unroll
    for (int bx = 0; bx < 8; bx++) o[bx] = acc[bx];
}

// ---------------------------------------------------------------------------
// Kernel 2: 1x1 init conv (256 -> 1024 ch) + depth-to-space scatter.
// ---------------------------------------------------------------------------
__global__ __launch_bounds__(256) void init_k(const float* __restrict__ csy,
                                              const float* __restrict__ Wi,
                                              float* __restrict__ irec)
{
    extern __shared__ float cs[];    // [256 c][64 pos]
    const int t = threadIdx.x;
    const int n = blockIdx.x;
    const int oc = blockIdx.y * 256 + t;

    const float* src = csy + n * 16384;
    for (int i = t; i < 16384; i += 256) cs[i] = src[i];
    __syncthreads();

    const float* wrow = Wi + oc * 256;
    const int ii = oc & 31;
    const int jj = oc >> 5;
    float* dst = irec + (n << 16);

#pragma unroll
    for (int pb = 0; pb < 64; pb += 32) {
        float acc[32];
#pragma unroll
        for (int p = 0; p < 32; p++) acc[p] = 0.f;
#pragma unroll 2
        for (int c = 0; c < 256; c++) {
            const float w = wrow[c];
            const float4* cp = (const float4*)&cs[c * 64 + pb];
#pragma unroll
            for (int p4 = 0; p4 < 8; p4++) {
                const float4 v = cp[p4];
                acc[p4 * 4 + 0] = fmaf(w, v.x, acc[p4 * 4 + 0]);
                acc[p4 * 4 + 1] = fmaf(w, v.y, acc[p4 * 4 + 1]);
                acc[p4 * 4 + 2] = fmaf(w, v.z, acc[p4 * 4 + 2]);
                acc[p4 * 4 + 3] = fmaf(w, v.w, acc[p4 * 4 + 3]);
            }
        }
#pragma unroll
        for (int p = 0; p < 32; p++) {
            const int pos = pb + p;
            const int h = pos >> 3, wq = pos & 7;
            dst[(h * 32 + ii) * 256 + wq * 32 + jj] = acc[p];
        }
    }
}

// ---------------------------------------------------------------------------
// Kernel 3 (scalar, used ONLY for the Cin=1 first conv): 3x3 conv, OC=64.
// ---------------------------------------------------------------------------
__global__ __launch_bounds__(256) void conv3x3_k(
    const float* __restrict__ in, const float* __restrict__ wgt,
    const float* __restrict__ res, const float* __restrict__ alpha_p,
    float* __restrict__ out, int Cin, int flags)
{
    extern __shared__ float sm3[];
    float* ws   = sm3;                 // Cin*576
    float* tile = sm3 + Cin * 576;     // 6*66 = 396

    const int t  = threadIdx.x;
    const int n  = blockIdx.z;
    const int y0 = blockIdx.y << 2;
    const int x0 = blockIdx.x << 6;

    const int wtot = Cin * 576;
    for (int i = t; i < wtot; i += 256) ws[i] = wgt[i];

    const int strip = t & 31;
    const int ocg   = t >> 5;
    const int sy    = strip >> 3;
    const int sxb   = (strip & 7) << 3;

    float acc[8][8];
#pragma unroll
    for (int o = 0; o < 8; o++)
#pragma unroll
        for (int p = 0; p < 8; p++) acc[o][p] = 0.f;

    const float* inN = in + (size_t)n * Cin * PLANE;
    const int Cin9 = Cin * 9;

    const int r0i = t / 66, c0i = t - r0i * 66;
    const int gy0 = y0 - 1 + r0i, gx0 = x0 - 1 + c0i;
    const bool ok0 = ((unsigned)gy0 < 256u) && ((unsigned)gx0 < 256u);
    const int off0 = gy0 * 256 + gx0;
    const int idx1 = t + 256;
    const bool has1 = idx1 < 396;
    const int r1i = idx1 / 66, c1i = idx1 - r1i * 66;
    const int gy1 = y0 - 1 + r1i, gx1 = x0 - 1 + c1i;
    const bool ok1 = has1 && ((unsigned)gy1 < 256u) && ((unsigned)gx1 < 256u);
    const int off1 = gy1 * 256 + gx1;

    float v0 = ok0 ? inN[off0] : 0.f;
    float v1 = ok1 ? inN[off1] : 0.f;

    for (int ic = 0; ic < Cin; ic++) {
        __syncthreads();
        tile[t] = v0;
        if (has1) tile[idx1] = v1;
        __syncthreads();
        if (ic + 1 < Cin) {
            const float* nx = inN + (ic + 1) * PLANE;
            v0 = ok0 ? nx[off0] : 0.f;
            v1 = ok1 ? nx[off1] : 0.f;
        }
        const float* wic = ws + (ocg << 3) * Cin9 + ic * 9;
#pragma unroll
        for (int ky = 0; ky < 3; ky++) {
#pragma unroll
            for (int kx = 0; kx < 3; kx++) {
                float inr[8];
                const float* tp = &tile[(sy + ky) * 66 + sxb + kx];
#pragma unroll
                for (int p = 0; p < 8; p++) inr[p] = tp[p];
#pragma unroll
                for (int o = 0; o < 8; o++) {
                    const float wv = wic[o * Cin9 + ky * 3 + kx];
#pragma unroll
                    for (int p = 0; p < 8; p++)
                        acc[o][p] = fmaf(wv, inr[p], acc[o][p]);
                }
            }
        }
    }

    const float alpha = *alpha_p;
    const int y = y0 + sy, xb = x0 + sxb;
#pragma unroll
    for (int o = 0; o < 8; o++) {
        const int oc = (ocg << 3) + o;
        const size_t gbase = (((size_t)(n * CHANS + oc)) << 16) + y * 256 + xb;
        float v[8];
#pragma unroll
        for (int p = 0; p < 8; p++) v[p] = acc[o][p];
        if (flags & F_RES) {
            const float4* rp = (const float4*)(res + gbase);
            const float4 r0 = rp[0], r1 = rp[1];
            v[0] += r0.x; v[1] += r0.y; v[2] += r0.z; v[3] += r0.w;
            v[4] += r1.x; v[5] += r1.y; v[6] += r1.z; v[7] += r1.w;
        }
        if (flags & F_PRELU) {
#pragma unroll
            for (int p = 0; p < 8; p++) v[p] = v[p] >= 0.f ? v[p] : alpha * v[p];
        }
        float4* op = (float4*)(out + gbase);
        op[0] = make_float4(v[0], v[1], v[2], v[3]);
        op[1] = make_float4(v[4], v[5], v[6], v[7]);
    }
}

// ---------------------------------------------------------------------------
// Kernel 3b: bf16x3 tensor-core 3x3 conv, Cin=64, OC=64, pad=1.
// Same verified implicit-GEMM mapping as the TF32 version, but with
// mma.m16n8k16.bf16 and error-compensated split:
//   D = Ah*Bh + Al*Bh + Ah*Bl   (hi = bf16(v), lo = bf16(v - hi))
// Block: M=256 px (64w x 4h) x N=64 oc, K = 64ic x 9 taps.
// 8 warps = 4 y-rows x 2 oc-halves; warp tile M=64 x N=32.
// K chunks of 16 ic; packed smem holds bf16x2 over adjacent ic.
// Smem (u32): ws_hi[32*9*68] | ws_lo | pk_hi[2][8*6*68] | pk_lo[2][...]
// ---------------------------------------------------------------------------
#define WPAD     68
#define WSU      19584            // 32 icpair * 9 tap * 68
#define TPLU     408              // per-icpair tile: 6 rows * 68 (u32)
#define CBUFU    3264             // 8 icpairs * TPLU
#define PKHI_OFF (2 * WSU)                 // 39168
#define PKLO_OFF (PKHI_OFF + 2 * CBUFU)    // 45696
#define SMEM_MMA3 ((PKLO_OFF + 2 * CBUFU) * 4)   // 52224 u32 = 208896 B

__device__ __forceinline__ void mma_bf16(float c[4], uint32_t a0, uint32_t a1,
                                         uint32_t a2, uint32_t a3,
                                         uint32_t b0, uint32_t b1)
{
    asm volatile(
        "mma.sync.aligned.m16n8k16.row.col.f32.bf16.bf16.f32 "
        "{%0,%1,%2,%3}, {%4,%5,%6,%7}, {%8,%9}, {%0,%1,%2,%3};\n"
        : "+f"(c[0]), "+f"(c[1]), "+f"(c[2]), "+f"(c[3])
        : "r"(a0), "r"(a1), "r"(a2), "r"(a3), "r"(b0), "r"(b1));
}

__device__ __forceinline__ void split_pack(float v0, float v1,
                                           uint32_t& hi, uint32_t& lo)
{
    __nv_bfloat16 h0 = __float2bfloat16_rn(v0);
    __nv_bfloat16 h1 = __float2bfloat16_rn(v1);
    float r0 = v0 - __bfloat162float(h0);
    float r1 = v1 - __bfloat162float(h1);
    __nv_bfloat16 l0 = __float2bfloat16_rn(r0);
    __nv_bfloat16 l1 = __float2bfloat16_rn(r1);
    hi = (uint32_t)__bfloat16_as_ushort(h0) |
         ((uint32_t)__bfloat16_as_ushort(h1) << 16);
    lo = (uint32_t)__bfloat16_as_ushort(l0) |
         ((uint32_t)__bfloat16_as_ushort(l1) << 16);
}

__global__ __launch_bounds__(256, 1) void conv3x3_mma3(
    const float* __restrict__ in, const float* __restrict__ wgt,
    const float* __restrict__ res, const float* __restrict__ alpha_p,
    float* __restrict__ out, int flags)
{
    extern __shared__ float sm[];
    uint32_t* smu = (uint32_t*)sm;
    uint32_t* whi = smu;
    uint32_t* wlo = smu + WSU;

    const int t    = threadIdx.x;
    const int lane = t & 31;
    const int wid  = t >> 5;
    const int n    = blockIdx.z;
    const int y0   = blockIdx.y << 2;
    const int x0   = blockIdx.x << 6;

    const int yrow = wid >> 1;        // output row this warp owns (0..3)
    const int wn   = (wid & 1) << 5;  // oc half: 0 / 32
    const int sA   = lane & 3;        // k-pair index within frag
    const int lq   = lane >> 2;       // 0..7

    // ---- stage weights, split into bf16 hi/lo, packed by adjacent-ic pairs:
    // dest u32 index = ((ic>>1)*9 + tap)*68 + oc, halfword = ic&1
    {
        unsigned short* wh16 = (unsigned short*)whi;
        unsigned short* wl16 = (unsigned short*)wlo;
        for (int i = t; i < 36864; i += 256) {
            const int oc  = i / 576;
            const int rem = i - oc * 576;
            const int ic  = rem / 9;
            const int tap = rem - ic * 9;
            const float w = wgt[i];
            __nv_bfloat16 h = __float2bfloat16_rn(w);
            __nv_bfloat16 l = __float2bfloat16_rn(w - __bfloat162float(h));
            const int di = (((ic >> 1) * 9 + tap) * WPAD + oc) * 2 + (ic & 1);
            wh16[di] = __bfloat16_as_ushort(h);
            wl16[di] = __bfloat16_as_ushort(l);
        }
    }

    const float* inN = in + (size_t)n * CHANS * PLANE;

    // ---- per-thread load/store coordinates for one 16-ic chunk
    // (8 icpairs x 6 rows x 66 cols = 3168 u32 positions, 13 strides of 256)
    int soff[13], goff[13];
    unsigned okm = 0;
#pragma unroll
    for (int s = 0; s < 13; s++) {
        const int idx = t + s * 256;
        if (idx < 3168) {
            const int j  = idx / 396;
            const int r2 = idx - j * 396;
            const int r  = r2 / 66;
            const int cc = r2 - r * 66;
            const int gy = y0 - 1 + r;
            const int gx = x0 - 1 + cc;
            if (((unsigned)gy < 256u) && ((unsigned)gx < 256u)) okm |= (1u << s);
            soff[s] = j * TPLU + r * WPAD + cc;
            goff[s] = (j << 1) * PLANE + gy * 256 + gx;   // ic = 2j
        } else { soff[s] = 0; goff[s] = 0; }
    }

    float acc[4][4][4];
#pragma unroll
    for (int mt = 0; mt < 4; mt++)
#pragma unroll
        for (int nt = 0; nt < 4; nt++)
#pragma unroll
            for (int i = 0; i < 4; i++) acc[mt][nt][i] = 0.f;

    // ---- prologue: load + pack chunk 0 into buffer 0
    float pf0[13], pf1[13];
#pragma unroll
    for (int s = 0; s < 13; s++) {
        const bool ok = (okm >> s) & 1;
        pf0[s] = ok ? inN[goff[s]] : 0.f;
        pf1[s] = ok ? inN[goff[s] + PLANE] : 0.f;
    }
    {
        uint32_t* ph = smu + PKHI_OFF;
        uint32_t* pl = smu + PKLO_OFF;
#pragma unroll
        for (int s = 0; s < 13; s++) {
            if (t + s * 256 < 3168) {
                uint32_t h, l;
                split_pack(pf0[s], pf1[s], h, l);
                ph[soff[s]] = h; pl[soff[s]] = l;
            }
        }
    }
    __syncthreads();   // covers weights + chunk0

    for (int c = 0; c < 4; c++) {
        // prefetch next chunk into regs (latency hidden by compute below)
        const bool more = (c < 3);
        if (more) {
            const float* src = inN + (c + 1) * 16 * PLANE;
#pragma unroll
            for (int s = 0; s < 13; s++) {
                const bool ok = (okm >> s) & 1;
                pf0[s] = ok ? src[goff[s]] : 0.f;
                pf1[s] = ok ? src[goff[s] + PLANE] : 0.f;
            }
        }

        const uint32_t* ph = smu + PKHI_OFF + (c & 1) * CBUFU;
        const uint32_t* pl = smu + PKLO_OFF + (c & 1) * CBUFU;
        const int wrow0 = (c << 3) + sA;     // icpair for b0 / a0,a1

#pragma unroll
        for (int tap = 0; tap < 9; tap++) {
            const int ky = tap / 3, kx = tap - ky * 3;
            const int rowoff = (yrow + ky) * WPAD + kx;

            // B fragments (k = ic): b0 from icpair wrow0, b1 from wrow0+4
            uint32_t bh0[4], bh1[4], bl0[4], bl1[4];
            const int wb = (wrow0 * 9 + tap) * WPAD + wn + lq;
#pragma unroll
            for (int nt = 0; nt < 4; nt++) {
                const int a = wb + nt * 8;
                bh0[nt] = whi[a];
                bh1[nt] = whi[a + 36 * WPAD];   // +4 icpairs * 9 taps * 68
                bl0[nt] = wlo[a];
                bl1[nt] = wlo[a + 36 * WPAD];
            }

#pragma unroll
            for (int mt = 0; mt < 4; mt++) {
                const int ao = sA * TPLU + rowoff + mt * 16 + lq;
                const uint32_t ah0 = ph[ao];
                const uint32_t ah1 = ph[ao + 8];
                const uint32_t ah2 = ph[ao + 4 * TPLU];
                const uint32_t ah3 = ph[ao + 4 * TPLU + 8];
                const uint32_t al0 = pl[ao];
                const uint32_t al1 = pl[ao + 8];
                const uint32_t al2 = pl[ao + 4 * TPLU];
                const uint32_t al3 = pl[ao + 4 * TPLU + 8];
#pragma unroll
                for (int nt = 0; nt < 4; nt++) {
                    mma_bf16(acc[mt][nt], ah0, ah1, ah2, ah3, bh0[nt], bh1[nt]);
                    mma_bf16(acc[mt][nt], al0, al1, al2, al3, bh0[nt], bh1[nt]);
                    mma_bf16(acc[mt][nt], ah0, ah1, ah2, ah3, bl0[nt], bl1[nt]);
                }
            }
        }

        // pack + store next chunk into the other buffer (distinct from read buf)
        if (more) {
            uint32_t* nh = smu + PKHI_OFF + ((c + 1) & 1) * CBUFU;
            uint32_t* nl = smu + PKLO_OFF + ((c + 1) & 1) * CBUFU;
#pragma unroll
            for (int s = 0; s < 13; s++) {
                if (t + s * 256 < 3168) {
                    uint32_t h, l;
                    split_pack(pf0[s], pf1[s], h, l);
                    nh[soff[s]] = h; nl[soff[s]] = l;
                }
            }
            __syncthreads();
        }
    }

    // ---- epilogue: residual add + PReLU (C-frag layout of m16n8)
    const float alpha = *alpha_p;
    const int gy = y0 + yrow;
#pragma unroll
    for (int mt = 0; mt < 4; mt++) {
#pragma unroll
        for (int nt = 0; nt < 4; nt++) {
#pragma unroll
            for (int i = 0; i < 4; i++) {
                const int oc = wn + nt * 8 + ((lane & 3) << 1) + (i & 1);
                const int x  = x0 + mt * 16 + lq + ((i >> 1) << 3);
                const size_t g = (((size_t)(n * CHANS + oc)) << 16) + gy * 256 + x;
                float v = acc[mt][nt][i];
                if (flags & F_RES) v += res[g];
                if (flags & F_PRELU) v = v >= 0.f ? v : alpha * v;
                out[g] = v;
            }
        }
    }
}

// ---------------------------------------------------------------------------
// Kernel 4: last conv: out = conv3x3(feat + broadcast(initrec), W_last).
// ---------------------------------------------------------------------------
__global__ __launch_bounds__(256) void last_k(const float* __restrict__ fin,
                                              const float* __restrict__ irec,
                                              const float* __restrict__ Wl,
                                              float* __restrict__ out)
{
    __shared__ float ws[585];
    __shared__ float tile[2340];  // 18 rows x 130

    const int t  = threadIdx.x;
    const int n  = blockIdx.z;
    const int y0 = blockIdx.y << 4;
    const int x0 = blockIdx.x << 7;

    for (int i = t; i < 576; i += 256) ws[i] = Wl[i];
    __syncthreads();
    if (t < 9) {
        float s = 0.f;
        for (int ic = 0; ic < 64; ic++) s += ws[ic * 9 + t];
        ws[576 + t] = s;
    }

    const int sy  = t >> 4;
    const int sxb = (t & 15) << 3;

    int offv[10]; bool okv[10]; bool hasv[10]; int idxv[10];
#pragma unroll
    for (int k = 0; k < 10; k++) {
        const int idx = t + k * 256;
        idxv[k] = idx;
        hasv[k] = idx < 2340;
        const int r = idx / 130, c = idx - r * 130;
        const int gy = y0 - 1 + r, gx = x0 - 1 + c;
        okv[k] = hasv[k] && ((unsigned)gy < 256u) && ((unsigned)gx < 256u);
        offv[k] = gy * 256 + gx;
    }

    float acc[8];
#pragma unroll
    for (int p = 0; p < 8; p++) acc[p] = 0.f;

    const float* src = fin + ((size_t)(n * CHANS) << 16);
    float pf[10];
#pragma unroll
    for (int k = 0; k < 10; k++) pf[k] = okv[k] ? src[offv[k]] : 0.f;

    for (int ic = 0; ic < 65; ic++) {
        __syncthreads();
#pragma unroll
        for (int k = 0; k < 10; k++) if (hasv[k]) tile[idxv[k]] = pf[k];
        __syncthreads();
        if (ic + 1 < 65) {
            const float* nx = (ic + 1 < 64)
                ? (fin + ((size_t)(n * CHANS + ic + 1) << 16))
                : (irec + ((size_t)n << 16));
#pragma unroll
            for (int k = 0; k < 10; k++) pf[k] = okv[k] ? nx[offv[k]] : 0.f;
        }
        float w[9];
#pragma unroll
        for (int q = 0; q < 9; q++) w[q] = ws[ic * 9 + q];
#pragma unroll
        for (int ky = 0; ky < 3; ky++) {
            float rv[10];
            const float* tp = &tile[(sy + ky) * 130 + sxb];
#pragma unroll
            for (int j = 0; j < 10; j++) rv[j] = tp[j];
#pragma unroll
            for (int kx = 0; kx < 3; kx++)
#pragma unroll
                for (int p = 0; p < 8; p++)
                    acc[p] = fmaf(rv[p + kx], w[ky * 3 + kx], acc[p]);
        }
    }

    const int y = y0 + sy, xb = x0 + sxb;
    float4* op = (float4*)(out + ((size_t)n << 16) + y * 256 + xb);
    op[0] = make_float4(acc[0], acc[1], acc[2], acc[3]);
    op[1] = make_float4(acc[4], acc[5], acc[6], acc[7]);
}

// ---------------------------------------------------------------------------
extern "C" void kernel_launch(void* const* d_in, const int* in_sizes, int n_in,
                              void* d_out_, int out_size)
{
    const float* x   = (const float*)d_in[0];
    const float* Wcs = (const float*)d_in[1];
    const float* Wi  = (const float*)d_in[2];
    const float* Wf  = (const float*)d_in[3];
    const float* Wb  = (const float*)d_in[4];
    const float* Wl  = (const float*)d_in[5];
    const float* am  = (const float*)d_in[6];
    const float* ab  = (const float*)d_in[7];

    float* out  = (float*)d_out_;
    float* csy  = out + CSY_OFF;
    float* irec = out + IR_OFF;

    float* fA = nullptr; float* fB = nullptr;
    cudaGetSymbolAddress((void**)&fA, g_featA);
    cudaGetSymbolAddress((void**)&fB, g_featB);

    cudaFuncSetAttribute(cs_k,        cudaFuncAttributeMaxDynamicSharedMemorySize, (8192 + 16384) * 4);
    cudaFuncSetAttribute(init_k,      cudaFuncAttributeMaxDynamicSharedMemorySize, 16384 * 4);
    cudaFuncSetAttribute(conv3x3_mma3,cudaFuncAttributeMaxDynamicSharedMemorySize, SMEM_MMA3);

    // 1) CS sampling -> outcsy (in d_out)
    cs_k<<<dim3(16, 8), 256, (8192 + 16384) * 4>>>(x, Wcs, csy);

    // 2) 1x1 init conv + depth-to-space -> out_initrec (in d_out)
    init_k<<<dim3(16, 4), 256, 16384 * 4>>>(csy, Wi, irec);

    // 3) first conv 1->64 + PReLU(a_main) -> featA (scalar fp32, Cin=1)
    conv3x3_k<<<dim3(4, 64, 16), 256, (1 * 576 + 396) * 4>>>(
        irec, Wf, nullptr, am, fA, 1, F_PRELU);

    // 4) 4x residual blocks with shared weights (bf16x3 tensor cores)
    for (int b = 0; b < 4; b++) {
        conv3x3_mma3<<<dim3(4, 64, 16), 256, SMEM_MMA3>>>(
            fA, Wb, nullptr, ab, fB, F_PRELU);
        conv3x3_mma3<<<dim3(4, 64, 16), 256, SMEM_MMA3>>>(
            fB, Wb, fA, ab, fA, F_PRELU | F_RES);
    }

    // 5) last conv (feat + broadcast initrec) 64->1 -> out
    last_k<<<dim3(2, 16, 16), 256>>>(fA, irec, Wl, out);
}